// round 1
// baseline (speedup 1.0000x reference)
#include <cuda_runtime.h>

#define N_MAX 100000
#define E_MAX 1200000
#define DIN   64
#define DHID  64
#define DOUT  34

// ---- scratch (allocation-free: __device__ globals) ----
__device__ int   g_deg [N_MAX];
__device__ float g_dinv[N_MAX];
__device__ float g_xw  [(size_t)N_MAX * DHID];  // x @ W1
__device__ float g_h   [(size_t)N_MAX * DHID];  // layer-1 aggregated output (atomic target)
__device__ float g_hw  [(size_t)N_MAX * DOUT];  // softmax(relu(h)) @ W2

// ---------------------------------------------------------------------------
__global__ void k_deg_init(int n) {
    int i = blockIdx.x * blockDim.x + threadIdx.x;
    if (i < n) g_deg[i] = 1;   // self-loop contributes 1 to in-degree
}

__global__ void k_deg_count(const int* __restrict__ dst, int e) {
    int i = blockIdx.x * blockDim.x + threadIdx.x;
    if (i < e) atomicAdd(&g_deg[dst[i]], 1);
}

__global__ void k_dinv(int n) {
    int i = blockIdx.x * blockDim.x + threadIdx.x;
    if (i < n) g_dinv[i] = rsqrtf((float)g_deg[i]);
}

// ---------------------------------------------------------------------------
// GEMM1: xw = x @ W1 ; h_init = b1 + dinv[i]^2 * xw[i]  (self-loop fused)
// Block = 256 thr (8 warps), each block handles 64 rows; warp-per-row.
__global__ void k_gemm1(const float* __restrict__ x,
                        const float* __restrict__ W1,
                        const float* __restrict__ b1, int n) {
    __shared__ float Ws[DIN * DHID];          // 16 KB
    __shared__ float xs[8][DIN];
    for (int i = threadIdx.x; i < DIN * DHID; i += blockDim.x) Ws[i] = W1[i];
    __syncthreads();

    int warp = threadIdx.x >> 5, lane = threadIdx.x & 31;
    int base = blockIdx.x * 64;
    for (int r = warp; r < 64; r += 8) {
        int row = base + r;
        if (row >= n) break;
        float2 xv = *(const float2*)(x + (size_t)row * DIN + lane * 2);
        xs[warp][lane * 2]     = xv.x;
        xs[warp][lane * 2 + 1] = xv.y;
        __syncwarp();
        float a0 = 0.f, a1 = 0.f;
#pragma unroll
        for (int k = 0; k < DIN; k++) {
            float xk = xs[warp][k];
            a0 = fmaf(xk, Ws[k * DHID + lane],      a0);
            a1 = fmaf(xk, Ws[k * DHID + lane + 32], a1);
        }
        float s = g_dinv[row]; s *= s;
        size_t o = (size_t)row * DHID;
        g_xw[o + lane]      = a0;
        g_xw[o + lane + 32] = a1;
        g_h [o + lane]      = fmaf(s, a0, b1[lane]);
        g_h [o + lane + 32] = fmaf(s, a1, b1[lane + 32]);
        __syncwarp();
    }
}

// ---------------------------------------------------------------------------
// Scatter layer 1: 16 lanes per edge (2 edges/warp). Coalesced 256B row gather,
// per-edge scalars broadcast from lanes 0/16.
__global__ void k_scatter1(const int* __restrict__ src,
                           const int* __restrict__ dst, int e) {
    int tid  = blockIdx.x * blockDim.x + threadIdx.x;
    int ei   = tid >> 4;
    bool act = ei < e;
    ei = act ? ei : (e - 1);
    int sub  = tid & 15;
    int lane = threadIdx.x & 31;

    int s = 0, d = 0; float nrm = 0.f;
    if (sub == 0) {
        s = src[ei]; d = dst[ei];
        nrm = g_dinv[s] * g_dinv[d];
    }
    s   = __shfl_sync(0xffffffffu, s,   lane & 16);
    d   = __shfl_sync(0xffffffffu, d,   lane & 16);
    nrm = __shfl_sync(0xffffffffu, nrm, lane & 16);
    if (!act) return;

    const float4 v = *(const float4*)(g_xw + (size_t)s * DHID + sub * 4);
    float* hp = g_h + (size_t)d * DHID + sub * 4;
    atomicAdd(hp + 0, v.x * nrm);
    atomicAdd(hp + 1, v.y * nrm);
    atomicAdd(hp + 2, v.z * nrm);
    atomicAdd(hp + 3, v.w * nrm);
}

// ---------------------------------------------------------------------------
// relu -> softmax(dim=1) -> @W2, plus out init = b2 + dinv^2 * hw (self-loop).
// Warp-per-row; W2 in smem.
__global__ void k_smax_gemm2(const float* __restrict__ W2,
                             const float* __restrict__ b2,
                             float* __restrict__ out, int n) {
    __shared__ float Ws[DHID * DOUT];         // 8.5 KB
    __shared__ float ps[8][DHID];
    for (int i = threadIdx.x; i < DHID * DOUT; i += blockDim.x) Ws[i] = W2[i];
    __syncthreads();

    int warp = threadIdx.x >> 5, lane = threadIdx.x & 31;
    int base = blockIdx.x * 64;
    for (int r = warp; r < 64; r += 8) {
        int row = base + r;
        if (row >= n) break;
        size_t o = (size_t)row * DHID;
        float2 hv = *(const float2*)(g_h + o + lane * 2);
        float v0 = fmaxf(hv.x, 0.f), v1 = fmaxf(hv.y, 0.f);
        float m = fmaxf(v0, v1);
#pragma unroll
        for (int off = 16; off; off >>= 1)
            m = fmaxf(m, __shfl_xor_sync(0xffffffffu, m, off));
        float e0 = __expf(v0 - m), e1 = __expf(v1 - m);
        float ssum = e0 + e1;
#pragma unroll
        for (int off = 16; off; off >>= 1)
            ssum += __shfl_xor_sync(0xffffffffu, ssum, off);
        float inv = 1.0f / ssum;
        ps[warp][lane * 2]     = e0 * inv;
        ps[warp][lane * 2 + 1] = e1 * inv;
        __syncwarp();

        // cols: lane (always < 34 since lane<=31), and lane+32 (valid for lane<2)
        int  c2    = lane + 32;
        bool has2  = (c2 < DOUT);
        int  c2c   = has2 ? c2 : (DOUT - 1);
        float acc0 = 0.f, acc1 = 0.f;
#pragma unroll
        for (int k = 0; k < DHID; k++) {
            float pk = ps[warp][k];
            acc0 = fmaf(pk, Ws[k * DOUT + lane], acc0);
            acc1 = fmaf(pk, Ws[k * DOUT + c2c],  acc1);
        }
        float s = g_dinv[row]; s *= s;
        size_t oo = (size_t)row * DOUT;
        g_hw[oo + lane] = acc0;
        out [oo + lane] = fmaf(s, acc0, b2[lane]);
        if (has2) {
            g_hw[oo + c2] = acc1;
            out [oo + c2] = fmaf(s, acc1, b2[c2]);
        }
        __syncwarp();
    }
}

// ---------------------------------------------------------------------------
// Scatter layer 2: 16 lanes per edge; lane `sub` handles float2 pair `sub`,
// lane 0 additionally handles pair 16 (features 32,33).
__global__ void k_scatter2(const int* __restrict__ src,
                           const int* __restrict__ dst,
                           float* __restrict__ out, int e) {
    int tid  = blockIdx.x * blockDim.x + threadIdx.x;
    int ei   = tid >> 4;
    bool act = ei < e;
    ei = act ? ei : (e - 1);
    int sub  = tid & 15;
    int lane = threadIdx.x & 31;

    int s = 0, d = 0; float nrm = 0.f;
    if (sub == 0) {
        s = src[ei]; d = dst[ei];
        nrm = g_dinv[s] * g_dinv[d];
    }
    s   = __shfl_sync(0xffffffffu, s,   lane & 16);
    d   = __shfl_sync(0xffffffffu, d,   lane & 16);
    nrm = __shfl_sync(0xffffffffu, nrm, lane & 16);
    if (!act) return;

    const float* hp = g_hw + (size_t)s * DOUT;
    float*       op = out  + (size_t)d * DOUT;
    float2 v = *(const float2*)(hp + sub * 2);   // 8B-aligned (34*4 ≡ 0 mod 8)
    atomicAdd(op + sub * 2,     v.x * nrm);
    atomicAdd(op + sub * 2 + 1, v.y * nrm);
    if (sub == 0) {
        float2 w = *(const float2*)(hp + 32);
        atomicAdd(op + 32, w.x * nrm);
        atomicAdd(op + 33, w.y * nrm);
    }
}

// ---------------------------------------------------------------------------
extern "C" void kernel_launch(void* const* d_in, const int* in_sizes, int n_in,
                              void* d_out, int out_size) {
    const float* x  = (const float*)d_in[0];
    const int*   ei = (const int*)  d_in[1];
    const float* W1 = (const float*)d_in[2];
    const float* b1 = (const float*)d_in[3];
    const float* W2 = (const float*)d_in[4];
    const float* b2 = (const float*)d_in[5];

    int n = in_sizes[0] / DIN;
    int e = in_sizes[1] / 2;
    const int* src = ei;
    const int* dst = ei + e;
    float* out = (float*)d_out;

    k_deg_init <<<(n + 255) / 256, 256>>>(n);
    k_deg_count<<<(e + 255) / 256, 256>>>(dst, e);
    k_dinv     <<<(n + 255) / 256, 256>>>(n);
    k_gemm1    <<<(n + 63) / 64, 256>>>(x, W1, b1, n);

    long t = (long)e * 16;
    k_scatter1 <<<(int)((t + 255) / 256), 256>>>(src, dst, e);
    k_smax_gemm2<<<(n + 63) / 64, 256>>>(W2, b2, out, n);
    k_scatter2 <<<(int)((t + 255) / 256), 256>>>(src, dst, out, e);
}

// round 2
// speedup vs baseline: 2.1265x; 2.1265x over previous
#include <cuda_runtime.h>

#define N_MAX 100000
#define E_MAX 1200000
#define DIN   64
#define DHID  64
#define DOUT  34
#define SCAN_BS 512
#define NB_MAX ((N_MAX + SCAN_BS - 1) / SCAN_BS)

// ---- scratch (allocation-free: __device__ globals) ----
__device__ int   g_deg [N_MAX];
__device__ float g_dinv[N_MAX];
__device__ int   g_off [N_MAX + 1];        // CSR offsets (real in-edges per dst)
__device__ int   g_cur [N_MAX];            // fill cursors
__device__ int   g_bsum[NB_MAX];           // scan block sums
__device__ int   g_esrc[E_MAX];            // CSR: src node per bucketed edge
__device__ float g_xw  [(size_t)N_MAX * DHID];  // x @ W1
__device__ float g_h   [(size_t)N_MAX * DHID];  // layer-1 output
__device__ float g_hw  [(size_t)N_MAX * DOUT];  // softmax(relu(h)) @ W2

// ---------------------------------------------------------------------------
__global__ void k_deg_init(int n) {
    int i = blockIdx.x * blockDim.x + threadIdx.x;
    if (i < n) g_deg[i] = 1;   // self-loop contributes 1 to in-degree
}

__global__ void k_deg_count(const int* __restrict__ dst, int e) {
    int i = blockIdx.x * blockDim.x + threadIdx.x;
    if (i < e) atomicAdd(&g_deg[dst[i]], 1);
}

__global__ void k_dinv(int n) {
    int i = blockIdx.x * blockDim.x + threadIdx.x;
    if (i < n) g_dinv[i] = rsqrtf((float)g_deg[i]);
}

// ---- exclusive scan of (deg-1) into g_off --------------------------------
__global__ void k_scan1(int n) {
    __shared__ int sh[SCAN_BS];
    int i = blockIdx.x * SCAN_BS + threadIdx.x;
    int v = (i < n) ? (g_deg[i] - 1) : 0;
    sh[threadIdx.x] = v;
    __syncthreads();
    for (int off = 1; off < SCAN_BS; off <<= 1) {
        int t = (threadIdx.x >= off) ? sh[threadIdx.x - off] : 0;
        __syncthreads();
        sh[threadIdx.x] += t;
        __syncthreads();
    }
    if (i < n) g_off[i] = sh[threadIdx.x] - v;            // exclusive (within block)
    if (threadIdx.x == SCAN_BS - 1) g_bsum[blockIdx.x] = sh[threadIdx.x];
}

__global__ void k_scan2(int nb, int n) {
    if (threadIdx.x == 0 && blockIdx.x == 0) {
        int run = 0;
        for (int b = 0; b < nb; b++) { int t = g_bsum[b]; g_bsum[b] = run; run += t; }
        g_off[n] = run;
    }
}

__global__ void k_scan3(int n) {
    int i = blockIdx.x * blockDim.x + threadIdx.x;
    if (i < n) {
        int o = g_off[i] + g_bsum[i / SCAN_BS];
        g_off[i] = o;
        g_cur[i] = o;
    }
}

__global__ void k_fill(const int* __restrict__ src, const int* __restrict__ dst, int e) {
    int i = blockIdx.x * blockDim.x + threadIdx.x;
    if (i < e) {
        int pos = atomicAdd(&g_cur[dst[i]], 1);
        g_esrc[pos] = src[i];
    }
}

// ---------------------------------------------------------------------------
// GEMM1: xw = x @ W1 ; g_h init = b1 + dinv^2 * xw  (self-loop fused).
// 4 rows x 2 cols register tile per lane; W row loads vectorized.
__global__ void k_gemm1(const float* __restrict__ x,
                        const float* __restrict__ W1,
                        const float* __restrict__ b1, int n) {
    __shared__ float Ws[DIN * DHID];          // 16 KB
    __shared__ float xs[8][4][DIN];           // 8 KB
    for (int i = threadIdx.x; i < DIN * DHID; i += blockDim.x) Ws[i] = W1[i];
    __syncthreads();

    int warp = threadIdx.x >> 5, lane = threadIdx.x & 31;
    int row0 = blockIdx.x * 32 + warp * 4;

#pragma unroll
    for (int r = 0; r < 4; r++) {
        int row = row0 + r;
        float2 xv = make_float2(0.f, 0.f);
        if (row < n) xv = *(const float2*)(x + (size_t)row * DIN + lane * 2);
        xs[warp][r][lane * 2]     = xv.x;
        xs[warp][r][lane * 2 + 1] = xv.y;
    }
    __syncwarp();

    float2 a[4];
#pragma unroll
    for (int r = 0; r < 4; r++) a[r] = make_float2(0.f, 0.f);

#pragma unroll
    for (int k = 0; k < DIN; k++) {
        float2 w = *(const float2*)(Ws + k * DHID + lane * 2);
#pragma unroll
        for (int r = 0; r < 4; r++) {
            float xk = xs[warp][r][k];
            a[r].x = fmaf(xk, w.x, a[r].x);
            a[r].y = fmaf(xk, w.y, a[r].y);
        }
    }

    float2 bb = *(const float2*)(b1 + lane * 2);
#pragma unroll
    for (int r = 0; r < 4; r++) {
        int row = row0 + r;
        if (row >= n) break;
        float s = g_dinv[row]; s *= s;
        size_t o = (size_t)row * DHID + lane * 2;
        *(float2*)(g_xw + o) = a[r];
        float2 h = make_float2(fmaf(s, a[r].x, bb.x), fmaf(s, a[r].y, bb.y));
        *(float2*)(g_h + o) = h;
    }
}

// ---------------------------------------------------------------------------
// Layer-1 aggregation: warp per dst node, no atomics.
// h[node] += dinv[node] * sum_{edges} dinv[src] * xw[src]
__global__ void k_agg1(int n) {
    int warp = threadIdx.x >> 5, lane = threadIdx.x & 31;
    int node = blockIdx.x * 8 + warp;
    if (node >= n) return;
    int beg = g_off[node], end = g_off[node + 1];

    float2 acc = make_float2(0.f, 0.f);
    for (int j = beg; j < end; j += 32) {
        int idx = j + lane;
        int s = 0; float w = 0.f;
        if (idx < end) { s = g_esrc[idx]; w = g_dinv[s]; }
        int m = min(32, end - j);
        for (int t = 0; t < m; t++) {
            int   ss = __shfl_sync(0xffffffffu, s, t);
            float ww = __shfl_sync(0xffffffffu, w, t);
            float2 v = *(const float2*)(g_xw + (size_t)ss * DHID + lane * 2);
            acc.x = fmaf(ww, v.x, acc.x);
            acc.y = fmaf(ww, v.y, acc.y);
        }
    }
    float dn = g_dinv[node];
    size_t o = (size_t)node * DHID + lane * 2;
    float2 h = *(float2*)(g_h + o);
    h.x = fmaf(dn, acc.x, h.x);
    h.y = fmaf(dn, acc.y, h.y);
    *(float2*)(g_h + o) = h;
}

// ---------------------------------------------------------------------------
// relu -> softmax(dim=1) -> @W2; out init = b2 + dinv^2 * hw (self-loop).
// 4-row tiling per warp.
__global__ void k_smax_gemm2(const float* __restrict__ W2,
                             const float* __restrict__ b2,
                             float* __restrict__ out, int n) {
    __shared__ float Ws[DHID * DOUT];         // 8.5 KB
    __shared__ float ps[8][4][DHID];          // 8 KB
    for (int i = threadIdx.x; i < DHID * DOUT; i += blockDim.x) Ws[i] = W2[i];
    __syncthreads();

    int warp = threadIdx.x >> 5, lane = threadIdx.x & 31;
    int row0 = blockIdx.x * 32 + warp * 4;

#pragma unroll
    for (int r = 0; r < 4; r++) {
        int row = row0 + r;
        float v0 = 0.f, v1 = 0.f;
        if (row < n) {
            float2 hv = *(const float2*)(g_h + (size_t)row * DHID + lane * 2);
            v0 = fmaxf(hv.x, 0.f); v1 = fmaxf(hv.y, 0.f);
        }
        float m = fmaxf(v0, v1);
#pragma unroll
        for (int off = 16; off; off >>= 1)
            m = fmaxf(m, __shfl_xor_sync(0xffffffffu, m, off));
        float e0 = __expf(v0 - m), e1 = __expf(v1 - m);
        float ssum = e0 + e1;
#pragma unroll
        for (int off = 16; off; off >>= 1)
            ssum += __shfl_xor_sync(0xffffffffu, ssum, off);
        float inv = 1.0f / ssum;
        ps[warp][r][lane * 2]     = e0 * inv;
        ps[warp][r][lane * 2 + 1] = e1 * inv;
    }
    __syncwarp();

    int  c2   = lane + 32;
    bool has2 = (c2 < DOUT);
    int  c2c  = has2 ? c2 : (DOUT - 1);
    float a0[4] = {0.f, 0.f, 0.f, 0.f};
    float a1[4] = {0.f, 0.f, 0.f, 0.f};
#pragma unroll
    for (int k = 0; k < DHID; k++) {
        float w0 = Ws[k * DOUT + lane];
        float w1 = Ws[k * DOUT + c2c];
#pragma unroll
        for (int r = 0; r < 4; r++) {
            float pk = ps[warp][r][k];
            a0[r] = fmaf(pk, w0, a0[r]);
            a1[r] = fmaf(pk, w1, a1[r]);
        }
    }

#pragma unroll
    for (int r = 0; r < 4; r++) {
        int row = row0 + r;
        if (row >= n) break;
        float s = g_dinv[row]; s *= s;
        size_t oo = (size_t)row * DOUT;
        g_hw[oo + lane] = a0[r];
        out [oo + lane] = fmaf(s, a0[r], b2[lane]);
        if (has2) {
            g_hw[oo + c2] = a1[r];
            out [oo + c2] = fmaf(s, a1[r], b2[c2]);
        }
    }
}

// ---------------------------------------------------------------------------
// Layer-2 aggregation: warp per dst node, no atomics.
__global__ void k_agg2(float* __restrict__ out, int n) {
    int warp = threadIdx.x >> 5, lane = threadIdx.x & 31;
    int node = blockIdx.x * 8 + warp;
    if (node >= n) return;
    int beg = g_off[node], end = g_off[node + 1];
    bool has2 = (lane < 2);

    float acc0 = 0.f, acc1 = 0.f;
    for (int j = beg; j < end; j += 32) {
        int idx = j + lane;
        int s = 0; float w = 0.f;
        if (idx < end) { s = g_esrc[idx]; w = g_dinv[s]; }
        int m = min(32, end - j);
        for (int t = 0; t < m; t++) {
            int   ss = __shfl_sync(0xffffffffu, s, t);
            float ww = __shfl_sync(0xffffffffu, w, t);
            const float* hp = g_hw + (size_t)ss * DOUT;
            acc0 = fmaf(ww, hp[lane], acc0);
            if (has2) acc1 = fmaf(ww, hp[lane + 32], acc1);
        }
    }
    float dn = g_dinv[node];
    size_t oo = (size_t)node * DOUT;
    out[oo + lane] = fmaf(dn, acc0, out[oo + lane]);
    if (has2) out[oo + lane + 32] = fmaf(dn, acc1, out[oo + lane + 32]);
}

// ---------------------------------------------------------------------------
extern "C" void kernel_launch(void* const* d_in, const int* in_sizes, int n_in,
                              void* d_out, int out_size) {
    const float* x  = (const float*)d_in[0];
    const int*   ei = (const int*)  d_in[1];
    const float* W1 = (const float*)d_in[2];
    const float* b1 = (const float*)d_in[3];
    const float* W2 = (const float*)d_in[4];
    const float* b2 = (const float*)d_in[5];

    int n = in_sizes[0] / DIN;
    int e = in_sizes[1] / 2;
    const int* src = ei;
    const int* dst = ei + e;
    float* out = (float*)d_out;

    int nb = (n + SCAN_BS - 1) / SCAN_BS;

    k_deg_init <<<(n + 255) / 256, 256>>>(n);
    k_deg_count<<<(e + 255) / 256, 256>>>(dst, e);
    k_dinv     <<<(n + 255) / 256, 256>>>(n);

    k_scan1<<<nb, SCAN_BS>>>(n);
    k_scan2<<<1, 32>>>(nb, n);
    k_scan3<<<(n + 255) / 256, 256>>>(n);
    k_fill <<<(e + 255) / 256, 256>>>(src, dst, e);

    k_gemm1<<<(n + 31) / 32, 256>>>(x, W1, b1, n);
    k_agg1 <<<(n + 7) / 8, 256>>>(n);
    k_smax_gemm2<<<(n + 31) / 32, 256>>>(W2, b2, out, n);
    k_agg2 <<<(n + 7) / 8, 256>>>(out, n);
}